// round 8
// baseline (speedup 1.0000x reference)
#include <cuda_runtime.h>
#include <cstdint>

#define NN3 262144
#define NN2 65536
#define NN1 16384

// Scratch (static device globals; no allocation allowed)
__device__ __align__(256) float g_x8 [NN3*16];
__device__ __align__(256) float g_x7p[NN2*16];
__device__ __align__(256) float g_x7 [NN2*32];
__device__ __align__(256) float g_x6p[NN1*32];
__device__ __align__(256) float g_x6 [NN1*64];
__device__ __align__(256) float g_x7d[NN2*32];
__device__ __align__(256) float g_x8d[NN3*16];

// ---------------- cp.async helpers ----------------
__device__ __forceinline__ void cp_async16(uint32_t dst, const void* src, int srcsize) {
    asm volatile("cp.async.cg.shared.global [%0], [%1], 16, %2;\n"
                 :: "r"(dst), "l"(src), "r"(srcsize) : "memory");
}
__device__ __forceinline__ void cp_commit() {
    asm volatile("cp.async.commit_group;\n" ::: "memory");
}
template<int N>
__device__ __forceinline__ void cp_wait() {
    asm volatile("cp.async.wait_group %0;\n" :: "n"(N) : "memory");
}

// ---------------- packed f32x2 helpers (Blackwell FFMA2) ----------------
__device__ __forceinline__ unsigned long long pack2(float x, float y) {
    unsigned long long r;
    asm("mov.b64 %0, {%1, %2};" : "=l"(r) : "f"(x), "f"(y));
    return r;
}
__device__ __forceinline__ void unpack2(float& x, float& y, unsigned long long v) {
    asm("mov.b64 {%0, %1}, %2;" : "=f"(x), "=f"(y) : "l"(v));
}
__device__ __forceinline__ void ffma2(unsigned long long& d, unsigned long long a, unsigned long long b) {
    asm("fma.rn.f32x2 %0, %1, %2, %0;" : "+l"(d) : "l"(a), "l"(b));
}

// =====================================================================
// conv3_k: streamed per-neighbor conv GEMM with
//   - warp-uniform weight reads (broadcast LDS)
//   - packed fma.rn.f32x2 accumulation (2x fp32 FMA throughput)
//   - double-buffered cp.async feat tiles
// Thread map: wid = tid/32; og = wid % OUTG (output group, warp-uniform);
//             g = (wid/OUTG)*32 + lane (node within group).
// out[n,c] = relu( sum_j sum_ci feat[(neigh[n,j])>>SHIFT, ci] * w[c, j*CIN+ci] + b[c] )
// =====================================================================
template<int CIN,int COUT,int TILE,int NT,int MT,int NTC,int SHIFT,bool RELU>
__global__ __launch_bounds__(NT)
void conv3_k(const float* __restrict__ feat, const int* __restrict__ neigh,
             const float* __restrict__ w, const float* __restrict__ b,
             float* __restrict__ out)
{
    constexpr int OUTG   = COUT / NTC;
    constexpr int NW     = NT / 32;
    constexpr int WPG    = NW / OUTG;
    constexpr int NG     = WPG * 32;
    static_assert(TILE == MT * NG, "tile shape");
    constexpr int KFULL  = 9 * CIN;
    constexpr int STRIDE = CIN + 4;           // floats; (STRIDE/4) odd -> conflict-free strided LDS.128
    static_assert(((STRIDE/4) & 1) == 1, "col stride must give odd quad step");
    constexpr int SW     = COUT + 4;          // wT row stride (floats, 16B-aligned rows)
    constexpr int CV     = CIN / 4;
    constexpr int GATHER = TILE * CV;
    constexpr int GPT    = GATHER / NT;
    constexpr int WPT    = (CIN * COUT) / NT;
    static_assert(GATHER % NT == 0 && (CIN*COUT) % NT == 0, "div");

    extern __shared__ float sm[];
    float* scol = sm;                           // [2][TILE*STRIDE]
    float* swt  = sm + 2*TILE*STRIDE;           // [2][CIN*SW]
    int*   sneigh = (int*)(swt + 2*CIN*SW);     // [TILE*9]

    const int tid  = threadIdx.x;
    const int base = blockIdx.x * TILE;
    const uint32_t scol_smem = (uint32_t)__cvta_generic_to_shared(scol);

    for (int i = tid; i < TILE*9; i += NT) {
        int n = neigh[(base + i/9)*9 + (i%9)];
        sneigh[i] = (n < 0) ? -1 : (n >> SHIFT);
    }
    __syncthreads();

    const int wid  = tid >> 5;
    const int lane = tid & 31;
    const int og   = wid % OUTG;
    const int g    = (wid / OUTG) * 32 + lane;
    const int c0   = og * NTC;

    float wreg[WPT];

    // ---- stage j=0 ----
    {
        #pragma unroll
        for (int i = 0; i < GPT; i++) {
            int e = i*NT + tid;
            int t = e / CV, q = e % CV;
            int n = sneigh[t*9 + 0];
            const float4* src = (n < 0) ? (const float4*)feat
                                        : (const float4*)feat + (size_t)n*CV + q;
            cp_async16(scol_smem + (uint32_t)((t*STRIDE + q*4)*4), src, (n < 0) ? 0 : 16);
        }
        cp_commit();
        #pragma unroll
        for (int i = 0; i < WPT; i++) {
            int e = i*NT + tid;
            int c = e % COUT, ci = e / COUT;
            wreg[i] = w[c*KFULL + 0*CIN + ci];
        }
        #pragma unroll
        for (int i = 0; i < WPT; i++) {
            int e = i*NT + tid;
            int c = e % COUT, ci = e / COUT;
            swt[ci*SW + c] = wreg[i];             // conflict-free: lanes write consecutive c
        }
    }

    unsigned long long acc[MT][NTC/2];
    #pragma unroll
    for (int m = 0; m < MT; m++)
        #pragma unroll
        for (int p = 0; p < NTC/2; p++) acc[m][p] = 0ull;

    #pragma unroll 1
    for (int j = 0; j < 9; j++) {
        const int bi = j & 1;

        if (j < 8) {
            #pragma unroll
            for (int i = 0; i < GPT; i++) {
                int e = i*NT + tid;
                int t = e / CV, q = e % CV;
                int n = sneigh[t*9 + (j+1)];
                const float4* src = (n < 0) ? (const float4*)feat
                                            : (const float4*)feat + (size_t)n*CV + q;
                cp_async16(scol_smem + (uint32_t)((((bi^1)*TILE + t)*STRIDE + q*4)*4),
                           src, (n < 0) ? 0 : 16);
            }
            cp_commit();
            #pragma unroll
            for (int i = 0; i < WPT; i++) {
                int e = i*NT + tid;
                int c = e % COUT, ci = e / COUT;
                wreg[i] = w[c*KFULL + (j+1)*CIN + ci];
            }
            cp_wait<1>();
        } else {
            cp_wait<0>();
        }
        __syncthreads();   // stage-j feat + weights visible

        // ---- compute stage j ----
        const float* colb = scol + bi*TILE*STRIDE;
        const float* wb   = swt  + bi*CIN*SW + c0;
        #pragma unroll
        for (int ci4 = 0; ci4 < CV; ci4++) {
            float4 cv[MT];
            #pragma unroll
            for (int m = 0; m < MT; m++)
                cv[m] = *(const float4*)&colb[(m*NG + g)*STRIDE + ci4*4];
            #pragma unroll
            for (int u = 0; u < 4; u++) {
                // broadcast weight row for k = ci4*4+u (all lanes same address)
                unsigned long long wp[NTC/2];
                #pragma unroll
                for (int q = 0; q < NTC/4; q++) {
                    float4 wv = *(const float4*)&wb[(ci4*4 + u)*SW + q*4];
                    wp[2*q+0] = pack2(wv.x, wv.y);
                    wp[2*q+1] = pack2(wv.z, wv.w);
                }
                #pragma unroll
                for (int m = 0; m < MT; m++) {
                    float v = (u==0) ? cv[m].x : (u==1) ? cv[m].y : (u==2) ? cv[m].z : cv[m].w;
                    unsigned long long vv = pack2(v, v);
                    #pragma unroll
                    for (int p = 0; p < NTC/2; p++)
                        ffma2(acc[m][p], vv, wp[p]);
                }
            }
        }

        // stash prefetched weights into the other buffer
        if (j < 8) {
            float* wdst = swt + (bi^1)*CIN*SW;
            #pragma unroll
            for (int i = 0; i < WPT; i++) {
                int e = i*NT + tid;
                int c = e % COUT, ci = e / COUT;
                wdst[ci*SW + c] = wreg[i];
            }
        }
        __syncthreads();   // stage-j buffers free for j+2 prefetch
    }

    // epilogue
    #pragma unroll
    for (int m = 0; m < MT; m++) {
        int node = base + m*NG + g;
        #pragma unroll
        for (int q = 0; q < NTC/4; q++) {
            float4 r;
            unpack2(r.x, r.y, acc[m][2*q+0]);
            unpack2(r.z, r.w, acc[m][2*q+1]);
            const float4 bv = *(const float4*)&b[c0 + q*4];
            r.x += bv.x; r.y += bv.y; r.z += bv.z; r.w += bv.w;
            if (RELU) {
                r.x = fmaxf(r.x, 0.f); r.y = fmaxf(r.y, 0.f);
                r.z = fmaxf(r.z, 0.f); r.w = fmaxf(r.w, 0.f);
            }
            *(float4*)&out[node*COUT + c0 + q*4] = r;
        }
    }
}

// =====================================================================
// Generic conv (enc1 CIN=1 and head COUT=1 edge layers)
// =====================================================================
template<int CIN,int COUT,int TILE,int NT,int SHIFT,bool RELU>
__global__ __launch_bounds__(NT)
void conv_k(const float* __restrict__ feat, const int* __restrict__ neigh,
            const float* __restrict__ w, const float* __restrict__ b,
            float* __restrict__ out)
{
    constexpr int K   = 9*CIN;
    constexpr int VEC = (CIN % 4 == 0) ? 4 : 1;
    constexpr int STRIDE = (VEC == 4) ? (K + 4) : ((K % 2 == 0) ? (K + 1) : K);
    constexpr int TPN   = NT / TILE;
    constexpr int CO_PER = COUT / TPN;

    extern __shared__ float sm[];
    float* swt  = sm;
    float* scol = sm + K*COUT;
    __shared__ int sneigh[TILE*9];

    const int tid  = threadIdx.x;
    const int base = blockIdx.x * TILE;

    for (int i = tid; i < K*COUT; i += NT) {
        int k = i / COUT, c = i % COUT;
        swt[i] = w[c*K + k];
    }
    for (int i = tid; i < TILE*9; i += NT) {
        int n = neigh[(base + i/9)*9 + (i%9)];
        sneigh[i] = (n < 0) ? -1 : (n >> SHIFT);
    }
    __syncthreads();

    if (VEC == 4) {
        constexpr int KV = K / 4;
        constexpr int CVv = CIN / 4;
        const float4* f4 = (const float4*)feat;
        for (int e = tid; e < TILE*KV; e += NT) {
            int t = e / KV, r = e % KV;
            int j = r / CVv;
            int n = sneigh[t*9 + j];
            float4 v = (n < 0) ? make_float4(0.f,0.f,0.f,0.f) : f4[n*CVv + (r % CVv)];
            *(float4*)&scol[t*STRIDE + r*4] = v;
        }
    } else {
        for (int e = tid; e < TILE*K; e += NT) {
            int t = e / K, r = e % K;
            int j = r / CIN, ci = r % CIN;
            int n = sneigh[t*9 + j];
            scol[t*STRIDE + r] = (n < 0) ? 0.f : feat[n*CIN + ci];
        }
    }
    __syncthreads();

    const int t  = tid / TPN;
    const int c0 = (tid % TPN) * CO_PER;
    float acc[CO_PER];
    #pragma unroll
    for (int c = 0; c < CO_PER; c++) acc[c] = 0.f;

    const float* colrow = &scol[t*STRIDE];
    #pragma unroll 4
    for (int k = 0; k < K; k++) {
        float v = colrow[k];
        #pragma unroll
        for (int c = 0; c < CO_PER; c++)
            acc[c] += v * swt[k*COUT + c0 + c];
    }

    const int node = base + t;
    #pragma unroll
    for (int c = 0; c < CO_PER; c++) {
        float r = acc[c] + __ldg(&b[c0 + c]);
        if (RELU) r = fmaxf(r, 0.f);
        out[node*COUT + c0 + c] = r;
    }
}

// Max-pool over 4 consecutive child rows (dense keys -> parent = i>>2).
template<int C>
__global__ void pool_k(const float* __restrict__ in, float* __restrict__ out, int NP)
{
    int i = blockIdx.x * blockDim.x + threadIdx.x;
    int total = NP * (C/4);
    if (i >= total) return;
    int p = i / (C/4), cq = i % (C/4);
    const float4* in4 = (const float4*)in;
    float4 a = in4[(4*p+0)*(C/4)+cq];
    float4 b = in4[(4*p+1)*(C/4)+cq];
    float4 c = in4[(4*p+2)*(C/4)+cq];
    float4 d = in4[(4*p+3)*(C/4)+cq];
    float4 r;
    r.x = fmaxf(fmaxf(a.x,b.x), fmaxf(c.x,d.x));
    r.y = fmaxf(fmaxf(a.y,b.y), fmaxf(c.y,d.y));
    r.z = fmaxf(fmaxf(a.z,b.z), fmaxf(c.z,d.z));
    r.w = fmaxf(fmaxf(a.w,b.w), fmaxf(c.w,d.w));
    ((float4*)out)[i] = r;
}

// smem sizes
template<int CIN,int COUT,int TILE>
static constexpr int conv3_smem() {
    return (2*TILE*(CIN+4) + 2*CIN*(COUT+4))*4 + TILE*9*4;
}
static constexpr int SM_ENC2 = conv3_smem<16,32,128>();   // ~29.7 KB
static constexpr int SM_ENC3 = conv3_smem<32,64,64>();    // ~38.2 KB
static constexpr int SM_DEC1 = conv3_smem<64,32,128>();   // ~92.7 KB
static constexpr int SM_DEC2 = conv3_smem<32,16,256>();   // ~88.0 KB
static constexpr int SM1 = (9*1*16   + 256*9  ) * 4;
static constexpr int SM6 = (9*16*1   + 128*148) * 4;

extern "C" void kernel_launch(void* const* d_in, const int* in_sizes, int n_in,
                              void* d_out, int out_size)
{
    const float* features = (const float*)d_in[0];
    const int* neighs3 = (const int*)d_in[4];
    const int* neighs2 = (const int*)d_in[5];
    const int* neighs1 = (const int*)d_in[6];
    const float* w_enc1 = (const float*)d_in[7];
    const float* b_enc1 = (const float*)d_in[8];
    const float* w_enc2 = (const float*)d_in[9];
    const float* b_enc2 = (const float*)d_in[10];
    const float* w_enc3 = (const float*)d_in[11];
    const float* b_enc3 = (const float*)d_in[12];
    const float* w_dec1 = (const float*)d_in[13];
    const float* b_dec1 = (const float*)d_in[14];
    const float* w_dec2 = (const float*)d_in[15];
    const float* b_dec2 = (const float*)d_in[16];
    const float* w_head = (const float*)d_in[17];
    const float* b_head = (const float*)d_in[18];
    float* out = (float*)d_out;

    float *x8, *x7p, *x7, *x6p, *x6, *x7d, *x8d;
    cudaGetSymbolAddress((void**)&x8,  g_x8);
    cudaGetSymbolAddress((void**)&x7p, g_x7p);
    cudaGetSymbolAddress((void**)&x7,  g_x7);
    cudaGetSymbolAddress((void**)&x6p, g_x6p);
    cudaGetSymbolAddress((void**)&x6,  g_x6);
    cudaGetSymbolAddress((void**)&x7d, g_x7d);
    cudaGetSymbolAddress((void**)&x8d, g_x8d);

    cudaFuncSetAttribute((const void*)conv_k<1,16,256,256,0,true>,        cudaFuncAttributeMaxDynamicSharedMemorySize, SM1);
    cudaFuncSetAttribute((const void*)conv3_k<16,32,128,256,2,8,0,true>,  cudaFuncAttributeMaxDynamicSharedMemorySize, SM_ENC2);
    cudaFuncSetAttribute((const void*)conv3_k<32,64,64,256,2,8,0,true>,   cudaFuncAttributeMaxDynamicSharedMemorySize, SM_ENC3);
    cudaFuncSetAttribute((const void*)conv3_k<64,32,128,256,2,8,2,true>,  cudaFuncAttributeMaxDynamicSharedMemorySize, SM_DEC1);
    cudaFuncSetAttribute((const void*)conv3_k<32,16,256,256,2,8,2,true>,  cudaFuncAttributeMaxDynamicSharedMemorySize, SM_DEC2);
    cudaFuncSetAttribute((const void*)conv_k<16,1,128,128,0,false>,       cudaFuncAttributeMaxDynamicSharedMemorySize, SM6);

    // enc1: [N3,1] -> x8 [N3,16]
    conv_k<1,16,256,256,0,true><<<NN3/256, 256, SM1>>>(features, neighs3, w_enc1, b_enc1, x8);
    // pool: x8 -> x7p [N2,16]
    pool_k<16><<<(NN2*4 + 255)/256, 256>>>(x8, x7p, NN2);
    // enc2: x7p -> x7 [N2,32]
    conv3_k<16,32,128,256,2,8,0,true><<<NN2/128, 256, SM_ENC2>>>(x7p, neighs2, w_enc2, b_enc2, x7);
    // pool: x7 -> x6p [N1,32]
    pool_k<32><<<(NN1*8 + 255)/256, 256>>>(x7, x6p, NN1);
    // enc3: x6p -> x6 [N1,64]
    conv3_k<32,64,64,256,2,8,0,true><<<NN1/64, 256, SM_ENC3>>>(x6p, neighs1, w_enc3, b_enc3, x6);
    // dec1 (fused unpool via neigh>>2): x6 -> x7d [N2,32]
    conv3_k<64,32,128,256,2,8,2,true><<<NN2/128, 256, SM_DEC1>>>(x6, neighs2, w_dec1, b_dec1, x7d);
    // dec2 (fused unpool): x7d -> x8d [N3,16]
    conv3_k<32,16,256,256,2,8,2,true><<<NN3/256, 256, SM_DEC2>>>(x7d, neighs3, w_dec2, b_dec2, x8d);
    // head: x8d -> out [N3,1]
    conv_k<16,1,128,128,0,false><<<NN3/128, 128, SM6>>>(x8d, neighs3, w_head, b_head, out);
}

// round 9
// speedup vs baseline: 1.0867x; 1.0867x over previous
#include <cuda_runtime.h>
#include <cstdint>

#define NN3 262144
#define NN2 65536
#define NN1 16384

// Scratch (static device globals; no allocation allowed)
__device__ __align__(256) float g_x8 [NN3*16];
__device__ __align__(256) float g_x7p[NN2*16];
__device__ __align__(256) float g_x7 [NN2*32];
__device__ __align__(256) float g_x6p[NN1*32];
__device__ __align__(256) float g_x6 [NN1*64];
__device__ __align__(256) float g_x7d[NN2*32];
__device__ __align__(256) float g_x8d[NN3*16];

// ---------------- cp.async helpers ----------------
__device__ __forceinline__ void cp_async16(uint32_t dst, const void* src, int srcsize) {
    asm volatile("cp.async.cg.shared.global [%0], [%1], 16, %2;\n"
                 :: "r"(dst), "l"(src), "r"(srcsize) : "memory");
}
__device__ __forceinline__ void cp_commit() {
    asm volatile("cp.async.commit_group;\n" ::: "memory");
}
template<int N>
__device__ __forceinline__ void cp_wait() {
    asm volatile("cp.async.wait_group %0;\n" :: "n"(N) : "memory");
}

// ---------------- packed f32x2 helpers ----------------
__device__ __forceinline__ unsigned long long pack2(float x, float y) {
    unsigned long long r;
    asm("mov.b64 %0, {%1, %2};" : "=l"(r) : "f"(x), "f"(y));
    return r;
}
__device__ __forceinline__ void unpack2(float& x, float& y, unsigned long long v) {
    asm("mov.b64 {%0, %1}, %2;" : "=f"(x), "=f"(y) : "l"(v));
}
__device__ __forceinline__ void ffma2(unsigned long long& d, unsigned long long a, unsigned long long b) {
    asm("fma.rn.f32x2 %0, %1, %2, %0;" : "+l"(d) : "l"(a), "l"(b));
}

// =====================================================================
// conv4_k: R7 structure (thread map og = tid%OUTG, g = tid/OUTG;
// double-buffered cp.async feat tiles; staged transposed weights) with
// NTC=8 outputs/thread consumed as MOV-free f32x2 pairs straight out of
// LDS.128 (weight rows are 16B-aligned; LDS.128 register quads give
// legally aligned 64-bit halves).
// out[n,c] = relu( sum_j sum_ci feat[(neigh[n,j])>>SHIFT, ci] * w[c, j*CIN+ci] + b[c] )
// =====================================================================
template<int CIN,int COUT,int NT,int MT,int SHIFT,bool RELU>
__global__ __launch_bounds__(NT)
void conv4_k(const float* __restrict__ feat, const int* __restrict__ neigh,
             const float* __restrict__ w, const float* __restrict__ b,
             float* __restrict__ out)
{
    constexpr int NTC    = 8;                 // outputs per thread (2x float4)
    constexpr int OUTG   = COUT / NTC;        // out groups
    constexpr int NG     = NT / OUTG;         // node groups
    constexpr int TILE   = MT * NG;
    constexpr int KFULL  = 9 * CIN;
    constexpr int STRIDE = CIN + 4;           // floats; 16B-multiple rows, conflict-free
    constexpr int SW     = COUT + 4;          // wT row stride; SW*4 bytes is a 16B multiple
    static_assert((STRIDE*4) % 16 == 0 && (SW*4) % 16 == 0, "align");
    constexpr int CV     = CIN / 4;
    constexpr int GATHER = TILE * CV;
    constexpr int GPT    = GATHER / NT;
    constexpr int WPT    = (CIN * COUT) / NT;
    static_assert(GATHER % NT == 0 && (CIN*COUT) % NT == 0, "div");

    extern __shared__ float sm[];
    float* scol = sm;                           // [2][TILE*STRIDE]
    float* swt  = sm + 2*TILE*STRIDE;           // [2][CIN*SW]
    int*   sneigh = (int*)(swt + 2*CIN*SW);     // [TILE*9]

    const int tid  = threadIdx.x;
    const int base = blockIdx.x * TILE;
    const uint32_t scol_smem = (uint32_t)__cvta_generic_to_shared(scol);

    for (int i = tid; i < TILE*9; i += NT) {
        int n = neigh[(base + i/9)*9 + (i%9)];
        sneigh[i] = (n < 0) ? -1 : (n >> SHIFT);
    }
    __syncthreads();

    const int og = tid % OUTG;        // out group (weight LDS: OUTG distinct quads, broadcast)
    const int g  = tid / OUTG;        // node (col LDS: NG/ distinct rows per warp, broadcast)
    const int c0 = og * NTC;

    float wreg[WPT];

    // ---- stage j=0 ----
    {
        #pragma unroll
        for (int i = 0; i < GPT; i++) {
            int e = i*NT + tid;
            int t = e / CV, q = e % CV;
            int n = sneigh[t*9 + 0];
            const float4* src = (n < 0) ? (const float4*)feat
                                        : (const float4*)feat + (size_t)n*CV + q;
            cp_async16(scol_smem + (uint32_t)((t*STRIDE + q*4)*4), src, (n < 0) ? 0 : 16);
        }
        cp_commit();
        #pragma unroll
        for (int i = 0; i < WPT; i++) {
            int e = i*NT + tid;
            int ci = e % CIN, c = e / CIN;
            wreg[i] = w[c*KFULL + 0*CIN + ci];
        }
        #pragma unroll
        for (int i = 0; i < WPT; i++) {
            int e = i*NT + tid;
            int ci = e % CIN, c = e / CIN;
            swt[ci*SW + c] = wreg[i];
        }
    }

    unsigned long long acc[MT][4];    // (c0+0,1)(c0+2,3)(c0+4,5)(c0+6,7) per node
    #pragma unroll
    for (int m = 0; m < MT; m++)
        #pragma unroll
        for (int p = 0; p < 4; p++) acc[m][p] = 0ull;

    #pragma unroll 1
    for (int j = 0; j < 9; j++) {
        const int bi = j & 1;

        if (j < 8) {
            #pragma unroll
            for (int i = 0; i < GPT; i++) {
                int e = i*NT + tid;
                int t = e / CV, q = e % CV;
                int n = sneigh[t*9 + (j+1)];
                const float4* src = (n < 0) ? (const float4*)feat
                                            : (const float4*)feat + (size_t)n*CV + q;
                cp_async16(scol_smem + (uint32_t)((((bi^1)*TILE + t)*STRIDE + q*4)*4),
                           src, (n < 0) ? 0 : 16);
            }
            cp_commit();
            #pragma unroll
            for (int i = 0; i < WPT; i++) {
                int e = i*NT + tid;
                int ci = e % CIN, c = e / CIN;
                wreg[i] = w[c*KFULL + (j+1)*CIN + ci];
            }
            cp_wait<1>();
        } else {
            cp_wait<0>();
        }
        __syncthreads();   // stage-j feat + weights visible

        // ---- compute stage j ----
        const float* colb = scol + bi*TILE*STRIDE;
        const float* wbp  = swt  + bi*CIN*SW + c0;
        #pragma unroll
        for (int ci4 = 0; ci4 < CV; ci4++) {
            float4 cv[MT];
            #pragma unroll
            for (int m = 0; m < MT; m++)
                cv[m] = *(const float4*)&colb[(m*NG + g)*STRIDE + ci4*4];
            #pragma unroll
            for (int u = 0; u < 4; u++) {
                // 8 warp-uniform-per-og weights, loaded as aligned 64-bit pairs (no movs)
                const ulonglong2 wA = *(const ulonglong2*)&wbp[(ci4*4 + u)*SW];
                const ulonglong2 wB = *(const ulonglong2*)&wbp[(ci4*4 + u)*SW + 4];
                #pragma unroll
                for (int m = 0; m < MT; m++) {
                    float v = (u==0) ? cv[m].x : (u==1) ? cv[m].y : (u==2) ? cv[m].z : cv[m].w;
                    unsigned long long vv = pack2(v, v);
                    ffma2(acc[m][0], vv, wA.x);
                    ffma2(acc[m][1], vv, wA.y);
                    ffma2(acc[m][2], vv, wB.x);
                    ffma2(acc[m][3], vv, wB.y);
                }
            }
        }

        // stash prefetched weights into the other buffer
        if (j < 8) {
            float* wdst = swt + (bi^1)*CIN*SW;
            #pragma unroll
            for (int i = 0; i < WPT; i++) {
                int e = i*NT + tid;
                int ci = e % CIN, c = e / CIN;
                wdst[ci*SW + c] = wreg[i];
            }
        }
        __syncthreads();   // stage-j buffers free for j+2 prefetch
    }

    // epilogue
    const float4 bv0 = *(const float4*)&b[c0];
    const float4 bv1 = *(const float4*)&b[c0 + 4];
    #pragma unroll
    for (int m = 0; m < MT; m++) {
        int node = base + m*NG + g;
        float4 r0, r1;
        unpack2(r0.x, r0.y, acc[m][0]);
        unpack2(r0.z, r0.w, acc[m][1]);
        unpack2(r1.x, r1.y, acc[m][2]);
        unpack2(r1.z, r1.w, acc[m][3]);
        r0.x += bv0.x; r0.y += bv0.y; r0.z += bv0.z; r0.w += bv0.w;
        r1.x += bv1.x; r1.y += bv1.y; r1.z += bv1.z; r1.w += bv1.w;
        if (RELU) {
            r0.x = fmaxf(r0.x, 0.f); r0.y = fmaxf(r0.y, 0.f);
            r0.z = fmaxf(r0.z, 0.f); r0.w = fmaxf(r0.w, 0.f);
            r1.x = fmaxf(r1.x, 0.f); r1.y = fmaxf(r1.y, 0.f);
            r1.z = fmaxf(r1.z, 0.f); r1.w = fmaxf(r1.w, 0.f);
        }
        *(float4*)&out[node*COUT + c0]     = r0;
        *(float4*)&out[node*COUT + c0 + 4] = r1;
    }
}

// =====================================================================
// Generic conv (enc1 CIN=1 and head COUT=1 edge layers)
// =====================================================================
template<int CIN,int COUT,int TILE,int NT,int SHIFT,bool RELU>
__global__ __launch_bounds__(NT)
void conv_k(const float* __restrict__ feat, const int* __restrict__ neigh,
            const float* __restrict__ w, const float* __restrict__ b,
            float* __restrict__ out)
{
    constexpr int K   = 9*CIN;
    constexpr int VEC = (CIN % 4 == 0) ? 4 : 1;
    constexpr int STRIDE = (VEC == 4) ? (K + 4) : ((K % 2 == 0) ? (K + 1) : K);
    constexpr int TPN   = NT / TILE;
    constexpr int CO_PER = COUT / TPN;

    extern __shared__ float sm[];
    float* swt  = sm;
    float* scol = sm + K*COUT;
    __shared__ int sneigh[TILE*9];

    const int tid  = threadIdx.x;
    const int base = blockIdx.x * TILE;

    for (int i = tid; i < K*COUT; i += NT) {
        int k = i / COUT, c = i % COUT;
        swt[i] = w[c*K + k];
    }
    for (int i = tid; i < TILE*9; i += NT) {
        int n = neigh[(base + i/9)*9 + (i%9)];
        sneigh[i] = (n < 0) ? -1 : (n >> SHIFT);
    }
    __syncthreads();

    if (VEC == 4) {
        constexpr int KV = K / 4;
        constexpr int CVv = CIN / 4;
        const float4* f4 = (const float4*)feat;
        for (int e = tid; e < TILE*KV; e += NT) {
            int t = e / KV, r = e % KV;
            int j = r / CVv;
            int n = sneigh[t*9 + j];
            float4 v = (n < 0) ? make_float4(0.f,0.f,0.f,0.f) : f4[n*CVv + (r % CVv)];
            *(float4*)&scol[t*STRIDE + r*4] = v;
        }
    } else {
        for (int e = tid; e < TILE*K; e += NT) {
            int t = e / K, r = e % K;
            int j = r / CIN, ci = r % CIN;
            int n = sneigh[t*9 + j];
            scol[t*STRIDE + r] = (n < 0) ? 0.f : feat[n*CIN + ci];
        }
    }
    __syncthreads();

    const int t  = tid / TPN;
    const int c0 = (tid % TPN) * CO_PER;
    float acc[CO_PER];
    #pragma unroll
    for (int c = 0; c < CO_PER; c++) acc[c] = 0.f;

    const float* colrow = &scol[t*STRIDE];
    #pragma unroll 4
    for (int k = 0; k < K; k++) {
        float v = colrow[k];
        #pragma unroll
        for (int c = 0; c < CO_PER; c++)
            acc[c] += v * swt[k*COUT + c0 + c];
    }

    const int node = base + t;
    #pragma unroll
    for (int c = 0; c < CO_PER; c++) {
        float r = acc[c] + __ldg(&b[c0 + c]);
        if (RELU) r = fmaxf(r, 0.f);
        out[node*COUT + c0 + c] = r;
    }
}

// Max-pool over 4 consecutive child rows (dense keys -> parent = i>>2).
template<int C>
__global__ void pool_k(const float* __restrict__ in, float* __restrict__ out, int NP)
{
    int i = blockIdx.x * blockDim.x + threadIdx.x;
    int total = NP * (C/4);
    if (i >= total) return;
    int p = i / (C/4), cq = i % (C/4);
    const float4* in4 = (const float4*)in;
    float4 a = in4[(4*p+0)*(C/4)+cq];
    float4 b = in4[(4*p+1)*(C/4)+cq];
    float4 c = in4[(4*p+2)*(C/4)+cq];
    float4 d = in4[(4*p+3)*(C/4)+cq];
    float4 r;
    r.x = fmaxf(fmaxf(a.x,b.x), fmaxf(c.x,d.x));
    r.y = fmaxf(fmaxf(a.y,b.y), fmaxf(c.y,d.y));
    r.z = fmaxf(fmaxf(a.z,b.z), fmaxf(c.z,d.z));
    r.w = fmaxf(fmaxf(a.w,b.w), fmaxf(c.w,d.w));
    ((float4*)out)[i] = r;
}

// smem sizes
template<int CIN,int COUT,int TILE>
static constexpr int conv4_smem() {
    return (2*TILE*(CIN+4) + 2*CIN*(COUT+4))*4 + TILE*9*4;
}
// conv4 TILE = MT * (NT/(COUT/8)) with NT=256, MT=2:
static constexpr int SM_ENC2 = conv4_smem<16,32,128>();   // ~30 KB  (TILE=128)
static constexpr int SM_ENC3 = conv4_smem<32,64,64>();    // ~38 KB  (TILE=64)
static constexpr int SM_DEC1 = conv4_smem<64,32,128>();   // ~93 KB  (TILE=128)
static constexpr int SM_DEC2 = conv4_smem<32,16,256>();   // ~88 KB  (TILE=256)
static constexpr int SM1 = (9*1*16   + 256*9  ) * 4;
static constexpr int SM6 = (9*16*1   + 128*148) * 4;

extern "C" void kernel_launch(void* const* d_in, const int* in_sizes, int n_in,
                              void* d_out, int out_size)
{
    const float* features = (const float*)d_in[0];
    const int* neighs3 = (const int*)d_in[4];
    const int* neighs2 = (const int*)d_in[5];
    const int* neighs1 = (const int*)d_in[6];
    const float* w_enc1 = (const float*)d_in[7];
    const float* b_enc1 = (const float*)d_in[8];
    const float* w_enc2 = (const float*)d_in[9];
    const float* b_enc2 = (const float*)d_in[10];
    const float* w_enc3 = (const float*)d_in[11];
    const float* b_enc3 = (const float*)d_in[12];
    const float* w_dec1 = (const float*)d_in[13];
    const float* b_dec1 = (const float*)d_in[14];
    const float* w_dec2 = (const float*)d_in[15];
    const float* b_dec2 = (const float*)d_in[16];
    const float* w_head = (const float*)d_in[17];
    const float* b_head = (const float*)d_in[18];
    float* out = (float*)d_out;

    float *x8, *x7p, *x7, *x6p, *x6, *x7d, *x8d;
    cudaGetSymbolAddress((void**)&x8,  g_x8);
    cudaGetSymbolAddress((void**)&x7p, g_x7p);
    cudaGetSymbolAddress((void**)&x7,  g_x7);
    cudaGetSymbolAddress((void**)&x6p, g_x6p);
    cudaGetSymbolAddress((void**)&x6,  g_x6);
    cudaGetSymbolAddress((void**)&x7d, g_x7d);
    cudaGetSymbolAddress((void**)&x8d, g_x8d);

    cudaFuncSetAttribute((const void*)conv_k<1,16,256,256,0,true>,    cudaFuncAttributeMaxDynamicSharedMemorySize, SM1);
    cudaFuncSetAttribute((const void*)conv4_k<16,32,256,2,0,true>,    cudaFuncAttributeMaxDynamicSharedMemorySize, SM_ENC2);
    cudaFuncSetAttribute((const void*)conv4_k<32,64,256,2,0,true>,    cudaFuncAttributeMaxDynamicSharedMemorySize, SM_ENC3);
    cudaFuncSetAttribute((const void*)conv4_k<64,32,256,2,2,true>,    cudaFuncAttributeMaxDynamicSharedMemorySize, SM_DEC1);
    cudaFuncSetAttribute((const void*)conv4_k<32,16,256,2,2,true>,    cudaFuncAttributeMaxDynamicSharedMemorySize, SM_DEC2);
    cudaFuncSetAttribute((const void*)conv_k<16,1,128,128,0,false>,   cudaFuncAttributeMaxDynamicSharedMemorySize, SM6);

    // enc1: [N3,1] -> x8 [N3,16]
    conv_k<1,16,256,256,0,true><<<NN3/256, 256, SM1>>>(features, neighs3, w_enc1, b_enc1, x8);
    // pool: x8 -> x7p [N2,16]
    pool_k<16><<<(NN2*4 + 255)/256, 256>>>(x8, x7p, NN2);
    // enc2: x7p -> x7 [N2,32]   (TILE=128)
    conv4_k<16,32,256,2,0,true><<<NN2/128, 256, SM_ENC2>>>(x7p, neighs2, w_enc2, b_enc2, x7);
    // pool: x7 -> x6p [N1,32]
    pool_k<32><<<(NN1*8 + 255)/256, 256>>>(x7, x6p, NN1);
    // enc3: x6p -> x6 [N1,64]   (TILE=64)
    conv4_k<32,64,256,2,0,true><<<NN1/64, 256, SM_ENC3>>>(x6p, neighs1, w_enc3, b_enc3, x6);
    // dec1 (fused unpool via neigh>>2): x6 -> x7d [N2,32]   (TILE=128)
    conv4_k<64,32,256,2,2,true><<<NN2/128, 256, SM_DEC1>>>(x6, neighs2, w_dec1, b_dec1, x7d);
    // dec2 (fused unpool): x7d -> x8d [N3,16]   (TILE=256)
    conv4_k<32,16,256,2,2,true><<<NN3/256, 256, SM_DEC2>>>(x7d, neighs3, w_dec2, b_dec2, x8d);
    // head: x8d -> out [N3,1]
    conv_k<16,1,128,128,0,false><<<NN3/128, 128, SM6>>>(x8d, neighs3, w_head, b_head, out);
}